// round 6
// baseline (speedup 1.0000x reference)
#include <cuda_runtime.h>

// Reverse (suffix) cumulative sum along dim=1.
// x: (B=2048, N=32768) fp32. out[b, j] = sum_{k >= j} x[b, k].
//
// R6: half-row CTAs for 2-CTA/SM residency (fill per-SM memory bubbles).
//   - 512 threads/CTA, each thread 8 float4 (coalesced interleaved layout),
//     CTA covers 16384 floats = half a row.
//   - blockIdx 0..rows-1   = RIGHT halves (cols [16384, 32768)): compute,
//     store, publish block total via __device__ scratch + release flag.
//   - blockIdx rows..2rows-1 = LEFT halves (cols [0, 16384)): load + local
//     scan fully overlap the wait; one thread polls the partner's flag
//     (partner has strictly lower blockIdx -> dispatched earlier -> no
//     deadlock), then carry is added to all outputs.
//   - flags cleared by a tiny kernel launched before the main one (both
//     graph-captured; __device__ globals, no allocation).

#define N_COLS      32768
#define HALF_COLS   16384
#define THREADS     512
#define F4_PER_WARP 256   // 1024 floats per warp tile
#define SLOTS       8     // float4s per thread
#define MAX_ROWS    4096

__device__ float    g_row_tot[MAX_ROWS];
__device__ unsigned g_row_flag[MAX_ROWS];

__global__ void clear_flags_kernel(int rows) {
    int i = blockIdx.x * blockDim.x + threadIdx.x;
    if (i < rows) g_row_flag[i] = 0u;
}

__global__ __launch_bounds__(THREADS, 2)
void revcumsum_half_kernel(const float* __restrict__ x,
                           float* __restrict__ out, int rows) {
    const int  bid      = blockIdx.x;
    const bool is_right = (bid < rows);
    const int  row      = is_right ? bid : bid - rows;
    const long long base =
        (long long)row * N_COLS + (is_right ? HALF_COLS : 0);

    const int t    = threadIdx.x;
    const int lane = t & 31;
    const int wid  = t >> 5;          // 0..15

    const float4* __restrict__ xin =
        reinterpret_cast<const float4*>(x + base) + wid * F4_PER_WARP + lane;

    // ---- coalesced load: slot i at float4 index i*32 + lane ----
    float4 r[SLOTS];
    #pragma unroll
    for (int i = 0; i < SLOTS; i++) r[i] = xin[i * 32];

    // ---- suffix scan inside each float4; s[i] = group sum ----
    float s[SLOTS];
    #pragma unroll
    for (int i = 0; i < SLOTS; i++) {
        r[i].z += r[i].w;
        r[i].y += r[i].z;
        r[i].x += r[i].y;
        s[i] = r[i].x;
    }

    // ---- per-slot warp suffix scan over lanes ----
    float excl[SLOTS];   // sum of s[i] for lanes > my lane
    float T[SLOTS];      // warp-wide total of slot i
    #pragma unroll
    for (int i = 0; i < SLOTS; i++) {
        float incl = s[i];
        #pragma unroll
        for (int d = 1; d < 32; d <<= 1) {
            float tmp = __shfl_down_sync(0xFFFFFFFFu, incl, d);
            if (lane + d < 32) incl += tmp;
        }
        excl[i] = incl - s[i];
        T[i]    = __shfl_sync(0xFFFFFFFFu, incl, 0);
    }

    // ---- register suffix over slots: O[i] = sum of T[i'] for i' > i ----
    float O[SLOTS];
    O[SLOTS - 1] = 0.0f;
    #pragma unroll
    for (int i = SLOTS - 2; i >= 0; i--) O[i] = O[i + 1] + T[i + 1];
    const float warp_total = O[0] + T[0];

    // ---- block scan over 16 warp totals + cross-CTA carry ----
    __shared__ float warp_tot[16];
    __shared__ float sh_carry;
    if (lane == 0) warp_tot[wid] = warp_total;
    if (t == 0) {
        if (is_right) {
            sh_carry = 0.0f;
        } else {
            // Wait for the partner (right-half) CTA's total. Partner has a
            // strictly lower blockIdx -> dispatched earlier -> no deadlock.
            volatile unsigned* vf = g_row_flag + row;
            while (*vf == 0u) { __nanosleep(64); }
            __threadfence();
            sh_carry = *((volatile float*)(g_row_tot + row));
        }
    }
    __syncthreads();

    float w  = (lane < 16) ? warp_tot[lane] : 0.0f;
    float iw = w;
    #pragma unroll
    for (int d = 1; d < 16; d <<= 1) {
        float tmp = __shfl_down_sync(0xFFFFFFFFu, iw, d);
        if (lane + d < 32) iw += tmp;
    }
    const float woff  = __shfl_sync(0xFFFFFFFFu, iw - w, wid);
    const float carry = sh_carry;

    // Right CTA publishes its block total (suffix at lane 0 == full sum).
    if (is_right && t == 0) {
        g_row_tot[row] = __shfl_sync(0xFFFFFFFFu, iw, 0);
    }
    // (shfl above is uniform across warp 0; re-fetch for t==0 done inside)

    // ---- apply offsets, coalesced store ----
    float4* __restrict__ o =
        reinterpret_cast<float4*>(out + base) + wid * F4_PER_WARP + lane;
    #pragma unroll
    for (int i = 0; i < SLOTS; i++) {
        const float off = carry + woff + O[i] + excl[i];
        float4 wv;
        wv.x = r[i].x + off;
        wv.y = r[i].y + off;
        wv.z = r[i].z + off;
        wv.w = r[i].w + off;
        o[i * 32] = wv;
    }

    // Release flag after total is globally visible.
    if (is_right && t == 0) {
        __threadfence();
        g_row_flag[row] = 1u;
    }
}

extern "C" void kernel_launch(void* const* d_in, const int* in_sizes, int n_in,
                              void* d_out, int out_size) {
    const float* x = (const float*)d_in[0];
    float* out = (float*)d_out;
    const int n    = in_sizes[0];       // B * N
    const int rows = n / N_COLS;        // 2048

    clear_flags_kernel<<<(rows + THREADS - 1) / THREADS, THREADS>>>(rows);
    revcumsum_half_kernel<<<2 * rows, THREADS>>>(x, out, rows);
}

// round 7
// speedup vs baseline: 1.0230x; 1.0230x over previous
#include <cuda_runtime.h>
#include <cstdint>

// Reverse (suffix) cumulative sum along dim=1.
// x: (2048, 32768) fp32. out[b, j] = sum_{k >= j} x[b, k].
//
// R7: persistent CTAs (atomic row ticket) + cp.async.bulk prefetch.
//  - 1024 threads/CTA, 1 CTA/SM. Each CTA loops over rows via a global
//    ticket (balanced, deterministic per-row math).
//  - While row r's stores drain, one thread bulk-copies the FIRST half
//    (64 KB) of row r+1 into smem (mbarrier complete_tx). Next iteration
//    warps 0-15 read that half via LDS.128 (on-chip), warps 16-31 LDG
//    the second half. This fills the per-row barrier bubble that capped
//    DRAM at ~76%.
//  - Same 3-level suffix scan as R5 (slot -> warp shfl -> block smem).

#define N_COLS     32768
#define HALF       16384
#define HALF_BYTES (HALF * 4)      // 65536
#define THREADS    1024
#define SLOTS      8
#define ROWS       2048
#define GRID       304

__device__ unsigned g_ticket;

__global__ void reset_ticket_kernel() { g_ticket = 0u; }

__device__ __forceinline__ uint32_t smem_u32(const void* p) {
    uint32_t a;
    asm("{ .reg .u64 t; cvta.to.shared.u64 t, %1; cvt.u32.u64 %0, t; }"
        : "=r"(a) : "l"(p));
    return a;
}

__device__ __forceinline__ void mbar_wait(uint32_t mbar, unsigned parity) {
    unsigned done = 0;
    while (!done) {
        asm volatile(
            "{ .reg .pred p;\n\t"
            "mbarrier.try_wait.parity.acquire.cta.shared::cta.b64 p, [%1], %2, 0x989680;\n\t"
            "selp.b32 %0, 1, 0, p; }"
            : "=r"(done) : "r"(mbar), "r"(parity) : "memory");
    }
}

__global__ __launch_bounds__(THREADS, 1)
void revcumsum_pipe_kernel(const float* __restrict__ x, float* __restrict__ out) {
    extern __shared__ float smem[];          // [HALF floats | 32 warp_tot | pad | mbar]
    float*    buf      = smem;               // 64 KB prefetch buffer
    float*    warp_tot = smem + HALF;        // 32 floats
    uint64_t* mbar_p   = (uint64_t*)(smem + HALF + 32 + 6);  // 8B-aligned (idx 16422? keep simple: +38 floats -> 152B off; realign below)
    // ensure 8B alignment explicitly:
    mbar_p = (uint64_t*)(((uintptr_t)(smem + HALF + 32) + 15) & ~(uintptr_t)15);

    __shared__ unsigned sh_row, sh_next;

    const int t    = threadIdx.x;
    const int lane = t & 31;
    const int wid  = t >> 5;

    const uint32_t mbar  = smem_u32(mbar_p);
    const uint32_t buf_s = smem_u32(buf);

    if (t == 0) {
        asm volatile("mbarrier.init.shared.b64 [%0], 1;" :: "r"(mbar) : "memory");
        sh_row = atomicAdd(&g_ticket, 1u);
    }
    __syncthreads();

    unsigned r      = sh_row;
    unsigned parity = 0;

    // Prefetch first half of our first row.
    if (r < ROWS && t == 0) {
        asm volatile("mbarrier.arrive.expect_tx.shared.b64 _, [%0], %1;"
                     :: "r"(mbar), "r"((unsigned)HALF_BYTES) : "memory");
        asm volatile(
            "cp.async.bulk.shared::cta.global.mbarrier::complete_tx::bytes [%0], [%1], %2, [%3];"
            :: "r"(buf_s), "l"(x + (size_t)r * N_COLS),
               "r"((unsigned)HALF_BYTES), "r"(mbar) : "memory");
    }

    while (r < ROWS) {
        if (t == 0) sh_next = atomicAdd(&g_ticket, 1u);

        // ---- gather this thread's 8 float4 slots ----
        float4 rg[SLOTS];
        if (wid < 16) {
            // First half: wait for the bulk copy, then LDS (conflict-free).
            mbar_wait(mbar, parity);
            const float4* bin = reinterpret_cast<const float4*>(buf) + wid * 256 + lane;
            #pragma unroll
            for (int i = 0; i < SLOTS; i++) rg[i] = bin[i * 32];
        } else {
            // Second half straight from global (f4 index wid*256 covers 4096..8191).
            const float4* xin =
                reinterpret_cast<const float4*>(x + (size_t)r * N_COLS) + wid * 256 + lane;
            #pragma unroll
            for (int i = 0; i < SLOTS; i++) rg[i] = xin[i * 32];
        }

        // ---- suffix scan inside each float4 ----
        float s[SLOTS];
        #pragma unroll
        for (int i = 0; i < SLOTS; i++) {
            rg[i].z += rg[i].w;
            rg[i].y += rg[i].z;
            rg[i].x += rg[i].y;
            s[i] = rg[i].x;
        }

        // ---- per-slot warp suffix scan over lanes ----
        float excl[SLOTS], T[SLOTS];
        #pragma unroll
        for (int i = 0; i < SLOTS; i++) {
            float incl = s[i];
            #pragma unroll
            for (int d = 1; d < 32; d <<= 1) {
                float tmp = __shfl_down_sync(0xFFFFFFFFu, incl, d);
                if (lane + d < 32) incl += tmp;
            }
            excl[i] = incl - s[i];
            T[i]    = __shfl_sync(0xFFFFFFFFu, incl, 0);
        }

        // ---- register suffix over slots ----
        float O[SLOTS];
        O[SLOTS - 1] = 0.0f;
        #pragma unroll
        for (int i = SLOTS - 2; i >= 0; i--) O[i] = O[i + 1] + T[i + 1];
        const float warp_total = O[0] + T[0];

        if (lane == 0) warp_tot[wid] = warp_total;
        __syncthreads();   // warp totals ready; all LDS of buf complete

        const unsigned nxt = sh_next;

        // Issue prefetch of next row's first half (buffer free now).
        if (t == 0 && nxt < ROWS) {
            asm volatile("mbarrier.arrive.expect_tx.shared.b64 _, [%0], %1;"
                         :: "r"(mbar), "r"((unsigned)HALF_BYTES) : "memory");
            asm volatile(
                "cp.async.bulk.shared::cta.global.mbarrier::complete_tx::bytes [%0], [%1], %2, [%3];"
                :: "r"(buf_s), "l"(x + (size_t)nxt * N_COLS),
                   "r"((unsigned)HALF_BYTES), "r"(mbar) : "memory");
        }

        // ---- block suffix scan over 32 warp totals (single barrier) ----
        float w  = warp_tot[lane];
        float iw = w;
        #pragma unroll
        for (int d = 1; d < 32; d <<= 1) {
            float tmp = __shfl_down_sync(0xFFFFFFFFu, iw, d);
            if (lane + d < 32) iw += tmp;
        }
        const float woff = __shfl_sync(0xFFFFFFFFu, iw - w, wid);

        // ---- apply offsets, coalesced store ----
        float4* o = reinterpret_cast<float4*>(out + (size_t)r * N_COLS) + wid * 256 + lane;
        #pragma unroll
        for (int i = 0; i < SLOTS; i++) {
            const float off = woff + O[i] + excl[i];
            float4 wv;
            wv.x = rg[i].x + off;
            wv.y = rg[i].y + off;
            wv.z = rg[i].z + off;
            wv.w = rg[i].w + off;
            o[i * 32] = wv;
        }

        // Barrier so no warp races ahead and overwrites warp_tot / sh_next
        // for the next iteration before slower warps have read them.
        __syncthreads();

        r = nxt;
        parity ^= 1;
    }
}

extern "C" void kernel_launch(void* const* d_in, const int* in_sizes, int n_in,
                              void* d_out, int out_size) {
    const float* x = (const float*)d_in[0];
    float* out = (float*)d_out;

    static bool attr_done = false;
    const int smem_bytes = HALF_BYTES + 1024;   // buffer + totals + mbar + pad
    if (!attr_done) {
        cudaFuncSetAttribute(revcumsum_pipe_kernel,
                             cudaFuncAttributeMaxDynamicSharedMemorySize, smem_bytes);
        attr_done = true;
    }

    reset_ticket_kernel<<<1, 1>>>();
    revcumsum_pipe_kernel<<<GRID, THREADS, smem_bytes>>>(x, out);
}